// round 4
// baseline (speedup 1.0000x reference)
#include <cuda_runtime.h>
#include <math.h>
#include <cstdint>

#define BB 256
#define TT 512
#define DD 256
#define HH 64
#define KTAG 32
#define GH 192      // 3*H
#define NCOMB 384   // fw 192 | bw 192

// Scratch (allocation-free rule: __device__ globals)
__device__ float g_xp[(size_t)BB * TT * NCOMB];      // [b,t, fw(z,r,h)|bw(z,r,h)]
__device__ float g_hidden[(size_t)BB * TT * 2 * HH]; // [b,t, fw64|bw64]
__device__ float g_Bt_hi[(size_t)NCOMB * DD];        // transposed weights, tf32 hi
__device__ float g_Bt_lo[(size_t)NCOMB * DD];        // tf32 lo

// packed fp32x2 helpers (GRU)
#define FFMA2(acc, a, b) \
    asm("fma.rn.f32x2 %0, %1, %2, %0;" : "+l"(acc) : "l"(a), "l"(b))
#define PACK2(out, lo, hi) \
    asm("mov.b64 %0, {%1, %2};" : "=l"(out) : "r"(__float_as_uint(lo)), "r"(__float_as_uint(hi)))
#define UNPACK2(lo, hi, in) \
    asm("mov.b64 {%0, %1}, %2;" : "=f"(lo), "=f"(hi) : "l"(in))

__device__ __forceinline__ float tf32_rna(float x) {
    uint32_t u;
    asm("cvt.rna.tf32.f32 %0, %1;" : "=r"(u) : "f"(x));
    return __uint_as_float(u);
}

// mma.sync m16n8k8 tf32 (sm_80+, compiles under compute_103)
#define MMA_TF32(c, a, b) \
    asm volatile("mma.sync.aligned.m16n8k8.row.col.f32.tf32.tf32.f32 " \
        "{%0,%1,%2,%3}, {%4,%5,%6,%7}, {%8,%9}, {%0,%1,%2,%3};" \
        : "+f"((c)[0]), "+f"((c)[1]), "+f"((c)[2]), "+f"((c)[3]) \
        : "r"((a)[0]), "r"((a)[1]), "r"((a)[2]), "r"((a)[3]), \
          "r"((b)[0]), "r"((b)[1]))

// ---------------------------------------------------------------------------
// K0: prep — transpose + tf32-split the combined input kernels: g_Bt[n][k]
// ---------------------------------------------------------------------------
__global__ void prep_b(const float* __restrict__ fwK, const float* __restrict__ bwK)
{
    int n = blockIdx.x;     // 0..383
    int k = threadIdx.x;    // 0..255
    float w = (n < GH) ? fwK[(size_t)k * GH + n] : bwK[(size_t)k * GH + (n - GH)];
    float hi = tf32_rna(w);
    float lo = tf32_rna(w - hi);
    g_Bt_hi[(size_t)n * DD + k] = hi;
    g_Bt_lo[(size_t)n * DD + k] = lo;
}

// ---------------------------------------------------------------------------
// K1: proj = X @ Bt^T + bias via split-TF32 mma.sync. CTA 128x128, BK=32.
// 8 warps = 2(M) x 4(N); warp tile 64x32. XOR-swizzled smem, conflict-free.
// smem layout (dynamic): Ahi 0 | Alo 16K | Bhi 32K | Blo 48K | bias 64K
// ---------------------------------------------------------------------------
#define SM_AHI 0
#define SM_ALO 16384
#define SM_BHI 32768
#define SM_BLO 49152
#define SM_BIAS 65536
#define SMEM_PROJ (65536 + 512)

__global__ __launch_bounds__(256) void proj_mma(
    const float* __restrict__ X,
    const float* __restrict__ fwB, const float* __restrict__ bwB)
{
    extern __shared__ __align__(16) char smem[];
    float* AhiF = (float*)(smem + SM_AHI);
    float* AloF = (float*)(smem + SM_ALO);
    float* BhiF = (float*)(smem + SM_BHI);
    float* BloF = (float*)(smem + SM_BLO);
    float* bias_sm = (float*)(smem + SM_BIAS);
    const uint32_t* AhiU = (const uint32_t*)AhiF;
    const uint32_t* AloU = (const uint32_t*)AloF;
    const uint32_t* BhiU = (const uint32_t*)BhiF;
    const uint32_t* BloU = (const uint32_t*)BloF;

    const int tid = threadIdx.x;
    const int w = tid >> 5;
    const int lane = tid & 31;
    const int g = lane >> 2;          // group 0..7
    const int x = lane & 3;           // 0..3
    const int warp_m = w & 1;         // 0..1
    const int warp_n = w >> 1;        // 0..3
    const int m_off = warp_m * 64;
    const int n_off = warp_n * 32;

    const int n0 = blockIdx.x * 128;  // 0,128,256
    const int m0 = blockIdx.y * 128;

    // bias for this n-block
    for (int i = tid; i < 128; i += 256) {
        int n = n0 + i;
        bias_sm[i] = (n < GH) ? fwB[n] : bwB[n - GH];
    }

    float C[4][4][4];
#pragma unroll
    for (int mt = 0; mt < 4; mt++)
#pragma unroll
        for (int nt = 0; nt < 4; nt++)
#pragma unroll
            for (int q = 0; q < 4; q++) C[mt][nt][q] = 0.f;

    const int lrow = tid >> 1;        // 0..127 (load row)
    const int half = tid & 1;         // 0..1   (16-float half of the 32-k slice)
    const int rxor = lrow & 7;

    // precompute fragment row bases
    int arow0[4], arow1[4];
#pragma unroll
    for (int mt = 0; mt < 4; mt++) {
        arow0[mt] = m_off + mt * 16 + g;
        arow1[mt] = arow0[mt] + 8;
    }
    int brow[4];
#pragma unroll
    for (int nt = 0; nt < 4; nt++) brow[nt] = n_off + nt * 8 + g;

    for (int ks = 0; ks < 8; ks++) {
        const int k0 = ks * 32;
        // ---- global -> smem (A: convert+split, B: pre-split copy)
        {
            const float* srcA = X + (size_t)(m0 + lrow) * DD + k0 + half * 16;
            const float* srcBh = g_Bt_hi + (size_t)(n0 + lrow) * DD + k0 + half * 16;
            const float* srcBl = g_Bt_lo + (size_t)(n0 + lrow) * DD + k0 + half * 16;
            const int base = lrow * 32;
#pragma unroll
            for (int i = 0; i < 4; i++) {
                int blk = half * 4 + i;
                int sb = ((blk ^ rxor) << 2);
                float4 v = ((const float4*)srcA)[i];
                float4 h, l;
                h.x = tf32_rna(v.x); l.x = tf32_rna(v.x - h.x);
                h.y = tf32_rna(v.y); l.y = tf32_rna(v.y - h.y);
                h.z = tf32_rna(v.z); l.z = tf32_rna(v.z - h.z);
                h.w = tf32_rna(v.w); l.w = tf32_rna(v.w - h.w);
                *(float4*)(AhiF + base + sb) = h;
                *(float4*)(AloF + base + sb) = l;
                *(float4*)(BhiF + base + sb) = ((const float4*)srcBh)[i];
                *(float4*)(BloF + base + sb) = ((const float4*)srcBl)[i];
            }
        }
        __syncthreads();

        // ---- compute: 4 k8 steps
#pragma unroll
        for (int k8 = 0; k8 < 4; k8++) {
            const int blkL = 2 * k8, blkH = 2 * k8 + 1;
            uint32_t ah[4][4], al[4][4];
#pragma unroll
            for (int mt = 0; mt < 4; mt++) {
                int r0 = arow0[mt], r1 = arow1[mt];
                int o0L = r0 * 32 + ((blkL ^ (r0 & 7)) << 2) + x;
                int o1L = r1 * 32 + ((blkL ^ (r1 & 7)) << 2) + x;
                int o0H = r0 * 32 + ((blkH ^ (r0 & 7)) << 2) + x;
                int o1H = r1 * 32 + ((blkH ^ (r1 & 7)) << 2) + x;
                ah[mt][0] = AhiU[o0L]; ah[mt][1] = AhiU[o1L];
                ah[mt][2] = AhiU[o0H]; ah[mt][3] = AhiU[o1H];
                al[mt][0] = AloU[o0L]; al[mt][1] = AloU[o1L];
                al[mt][2] = AloU[o0H]; al[mt][3] = AloU[o1H];
            }
#pragma unroll
            for (int nt = 0; nt < 4; nt++) {
                int nn = brow[nt];
                int oL = nn * 32 + ((blkL ^ (nn & 7)) << 2) + x;
                int oH = nn * 32 + ((blkH ^ (nn & 7)) << 2) + x;
                uint32_t bh[2], bl[2];
                bh[0] = BhiU[oL]; bh[1] = BhiU[oH];
                bl[0] = BloU[oL]; bl[1] = BloU[oH];
#pragma unroll
                for (int mt = 0; mt < 4; mt++) {
                    MMA_TF32(C[mt][nt], ah[mt], bh);
                    MMA_TF32(C[mt][nt], ah[mt], bl);
                    MMA_TF32(C[mt][nt], al[mt], bh);
                }
            }
        }
        __syncthreads();
    }

    // ---- epilogue: +bias, store
#pragma unroll
    for (int mt = 0; mt < 4; mt++) {
        int r0 = m0 + m_off + mt * 16 + g;
#pragma unroll
        for (int nt = 0; nt < 4; nt++) {
            int col = n_off + nt * 8 + 2 * x;
            float b0 = bias_sm[col], b1 = bias_sm[col + 1];
            float2 v0 = make_float2(C[mt][nt][0] + b0, C[mt][nt][1] + b1);
            float2 v1 = make_float2(C[mt][nt][2] + b0, C[mt][nt][3] + b1);
            *(float2*)(g_xp + (size_t)r0 * NCOMB + n0 + col) = v0;
            *(float2*)(g_xp + (size_t)(r0 + 8) * NCOMB + n0 + col) = v1;
        }
    }
}

// ---------------------------------------------------------------------------
// K2: GRU recurrence (unchanged, known-passing)
// ---------------------------------------------------------------------------
__global__ __launch_bounds__(192) void gru_kernel(
    const float* __restrict__ rec_fw, const float* __restrict__ rec_bw,
    const float* __restrict__ bias_fw, const float* __restrict__ bias_bw,
    const int* __restrict__ mask)
{
    __shared__ float h_sm[HH];
    __shared__ float hp_sm[GH];

    int b = blockIdx.x;
    int dir = blockIdx.y;
    int j = threadIdx.x;

    const float* rec = dir ? rec_bw : rec_fw;
    unsigned long long rp[HH / 2];
#pragma unroll
    for (int i = 0; i < HH / 2; i++) {
        float r0 = rec[(2 * i) * GH + j];
        float r1 = rec[(2 * i + 1) * GH + j];
        PACK2(rp[i], r0, r1);
    }
    float brj = (dir ? bias_bw : bias_fw)[GH + j];

    if (j < HH) h_sm[j] = 0.f;
    __syncthreads();

    const int gate = (j < HH);
    float pxz = 0.f, pxr = 0.f, pxh = 0.f;
    int pm = 1;
    if (gate) {
        int tt = dir ? (TT - 1) : 0;
        const float* xr0 = g_xp + ((size_t)b * TT + tt) * NCOMB + dir * GH;
        pxz = xr0[j]; pxr = xr0[HH + j]; pxh = xr0[2 * HH + j];
        pm = mask[b * TT + tt];
    }

    for (int t = 0; t < TT; t++) {
        unsigned long long accA = 0ULL, accB = 0ULL;
        const unsigned long long* h2 = (const unsigned long long*)h_sm;
#pragma unroll
        for (int i = 0; i < HH / 2; i += 2) {
            FFMA2(accA, rp[i], h2[i]);
            FFMA2(accB, rp[i + 1], h2[i + 1]);
        }
        float a0, a1, b0, b1;
        UNPACK2(a0, a1, accA);
        UNPACK2(b0, b1, accB);
        hp_sm[j] = (a0 + a1) + (b0 + b1) + brj;
        __syncthreads();

        if (gate) {
            int tt = dir ? (TT - 1 - t) : t;
            float hz = hp_sm[j];
            float hr = hp_sm[HH + j];
            float hc = hp_sm[2 * HH + j];
            float hprev = h_sm[j];
            float z = 1.f / (1.f + expf(-(pxz + hz)));
            float r = 1.f / (1.f + expf(-(pxr + hr)));
            float c = tanhf(pxh + r * hc);
            float hn = z * hprev + (1.f - z) * c;
            if (pm <= 0) hn = hprev;
            h_sm[j] = hn;
            g_hidden[((size_t)b * TT + tt) * (2 * HH) + dir * HH + j] = hn;
            if (t + 1 < TT) {
                int tn = dir ? (TT - 2 - t) : (t + 1);
                const float* xr = g_xp + ((size_t)b * TT + tn) * NCOMB + dir * GH;
                pxz = xr[j]; pxr = xr[HH + j]; pxh = xr[2 * HH + j];
                pm = mask[b * TT + tn];
            }
        }
        __syncthreads();
    }
}

// ---------------------------------------------------------------------------
// K3: potentials (unchanged)
// ---------------------------------------------------------------------------
__global__ __launch_bounds__(256) void pot_kernel(
    const float* __restrict__ dk, const float* __restrict__ db,
    const float* __restrict__ lb, const float* __restrict__ rb,
    float* __restrict__ pot)
{
    __shared__ float ds[2 * HH * KTAG];
    __shared__ float rows[8][2 * HH];

    int tid = threadIdx.x;
    for (int i = tid; i < 2 * HH * KTAG; i += 256) ds[i] = dk[i];

    int w = tid >> 5, lane = tid & 31;
    size_t row0 = (size_t)blockIdx.x * 8;

    {
        int r = tid >> 5;
        int c4 = (tid & 31) * 4;
        *(float4*)&rows[r][c4] =
            *(const float4*)(g_hidden + (row0 + r) * (2 * HH) + c4);
    }
    __syncthreads();

    float acc = db[lane];
#pragma unroll
    for (int h4 = 0; h4 < 32; h4++) {
        float4 hv = *(const float4*)&rows[w][h4 * 4];
        acc = fmaf(hv.x, ds[(4 * h4 + 0) * KTAG + lane], acc);
        acc = fmaf(hv.y, ds[(4 * h4 + 1) * KTAG + lane], acc);
        acc = fmaf(hv.z, ds[(4 * h4 + 2) * KTAG + lane], acc);
        acc = fmaf(hv.w, ds[(4 * h4 + 3) * KTAG + lane], acc);
    }
    size_t row = row0 + w;
    int t = (int)(row % TT);
    if (t == 0)      acc += lb[lane];
    if (t == TT - 1) acc += rb[lane];
    pot[row * KTAG + lane] = acc;
}

// ---------------------------------------------------------------------------
// K4: Viterbi (unchanged)
// ---------------------------------------------------------------------------
__device__ __forceinline__ void amerge(float& mv, int& mi, float v, int i)
{
    if (v > mv || (v == mv && i < mi)) { mv = v; mi = i; }
}

__global__ __launch_bounds__(32) void viterbi_kernel(
    const float* __restrict__ pot, const float* __restrict__ trans,
    const int* __restrict__ mask,
    float* __restrict__ out_dec, float* __restrict__ out_len)
{
    __shared__ unsigned char bp[TT][KTAG];
    __shared__ unsigned char dec[TT];

    int b = blockIdx.x, k = threadIdx.x;

    float tr[KTAG];
#pragma unroll
    for (int j = 0; j < KTAG; j++) tr[j] = trans[j * KTAG + k];

    const float* pb = pot + (size_t)b * TT * KTAG;
    float s = pb[k];

    for (int t0 = 1; t0 < TT; t0 += 8) {
        float pv[8];
#pragma unroll
        for (int u = 0; u < 8; u++) {
            int t = t0 + u;
            pv[u] = (t < TT) ? pb[(size_t)t * KTAG + k] : 0.f;
        }
#pragma unroll
        for (int u = 0; u < 8; u++) {
            int t = t0 + u;
            if (t >= TT) break;
            float m0 = -INFINITY, m1 = -INFINITY, m2 = -INFINITY, m3 = -INFINITY;
            int i0 = 0, i1 = 1, i2 = 2, i3 = 3;
#pragma unroll
            for (int j = 0; j < KTAG; j += 4) {
                float v0 = __shfl_sync(0xffffffffu, s, j)     + tr[j];
                float v1 = __shfl_sync(0xffffffffu, s, j + 1) + tr[j + 1];
                float v2 = __shfl_sync(0xffffffffu, s, j + 2) + tr[j + 2];
                float v3 = __shfl_sync(0xffffffffu, s, j + 3) + tr[j + 3];
                if (v0 > m0) { m0 = v0; i0 = j; }
                if (v1 > m1) { m1 = v1; i1 = j + 1; }
                if (v2 > m2) { m2 = v2; i2 = j + 2; }
                if (v3 > m3) { m3 = v3; i3 = j + 3; }
            }
            amerge(m0, i0, m1, i1);
            amerge(m2, i2, m3, i3);
            amerge(m0, i0, m2, i2);
            s = m0 + pv[u];
            bp[t][k] = (unsigned char)i0;
        }
    }

    float m0 = -INFINITY, m1 = -INFINITY, m2 = -INFINITY, m3 = -INFINITY;
    int i0 = 0, i1 = 1, i2 = 2, i3 = 3;
#pragma unroll
    for (int j = 0; j < KTAG; j += 4) {
        float v0 = __shfl_sync(0xffffffffu, s, j);
        float v1 = __shfl_sync(0xffffffffu, s, j + 1);
        float v2 = __shfl_sync(0xffffffffu, s, j + 2);
        float v3 = __shfl_sync(0xffffffffu, s, j + 3);
        if (v0 > m0) { m0 = v0; i0 = j; }
        if (v1 > m1) { m1 = v1; i1 = j + 1; }
        if (v2 > m2) { m2 = v2; i2 = j + 2; }
        if (v3 > m3) { m3 = v3; i3 = j + 3; }
    }
    amerge(m0, i0, m1, i1);
    amerge(m2, i2, m3, i3);
    amerge(m0, i0, m2, i2);

    __syncwarp();
    if (k == 0) {
        int tag = i0;
        dec[TT - 1] = (unsigned char)tag;
        for (int t = TT - 2; t >= 0; t--) {
            tag = bp[t + 1][tag];
            dec[t] = (unsigned char)tag;
        }
    }
    __syncwarp();

    for (int t = k; t < TT; t += 32)
        out_dec[(size_t)b * TT + t] = (float)dec[t];

    int sum = 0;
    for (int t = k; t < TT; t += 32) sum += mask[(size_t)b * TT + t];
#pragma unroll
    for (int o = 16; o > 0; o >>= 1) sum += __shfl_down_sync(0xffffffffu, sum, o);
    if (k == 0) out_len[b] = (float)sum;
}

// K5: copy chain_kernel into the output tail
__global__ void tail_kernel(const float* __restrict__ chain, float* __restrict__ outc)
{
    int i = threadIdx.x + blockIdx.x * blockDim.x;
    if (i < KTAG * KTAG) outc[i] = chain[i];
}

// ---------------------------------------------------------------------------
extern "C" void kernel_launch(void* const* d_in, const int* in_sizes, int n_in,
                              void* d_out, int out_size)
{
    const float* X      = (const float*)d_in[0];
    const int*   mask   = (const int*)d_in[1];
    const float* fwK    = (const float*)d_in[2];
    const float* fwR    = (const float*)d_in[3];
    const float* fwBias = (const float*)d_in[4];
    const float* bwK    = (const float*)d_in[5];
    const float* bwR    = (const float*)d_in[6];
    const float* bwBias = (const float*)d_in[7];
    const float* dK     = (const float*)d_in[8];
    const float* dB     = (const float*)d_in[9];
    const float* chain  = (const float*)d_in[10];
    const float* lb     = (const float*)d_in[11];
    const float* rb     = (const float*)d_in[12];

    float* out       = (float*)d_out;
    float* out_dec   = out;                              // B*T
    float* pot       = out + (size_t)BB * TT;            // B*T*K
    float* out_len   = pot + (size_t)BB * TT * KTAG;     // B
    float* out_chain = out_len + BB;                     // K*K

    cudaFuncSetAttribute(proj_mma, cudaFuncAttributeMaxDynamicSharedMemorySize, SMEM_PROJ);

    prep_b<<<NCOMB, 256>>>(fwK, bwK);
    dim3 gp(NCOMB / 128, (BB * TT) / 128);
    proj_mma<<<gp, 256, SMEM_PROJ>>>(X, fwBias, bwBias);
    dim3 g2(BB, 2);
    gru_kernel<<<g2, GH>>>(fwR, bwR, fwBias, bwBias, mask);
    pot_kernel<<<(BB * TT) / 8, 256>>>(dK, dB, lb, rb, pot);
    viterbi_kernel<<<BB, 32>>>(pot, chain, mask, out_dec, out_len);
    tail_kernel<<<4, 256>>>(chain, out_chain);
}

// round 5
// speedup vs baseline: 1.0172x; 1.0172x over previous
#include <cuda_runtime.h>
#include <cuda_bf16.h>
#include <math.h>
#include <cstdint>

#define BB 256
#define TT 512
#define DD 256
#define HH 64
#define KTAG 32
#define GH 192      // 3*H
#define NCOMB 384   // fw 192 | bw 192

// Scratch (allocation-free rule: __device__ globals)
__device__ float g_xp[(size_t)BB * TT * NCOMB];      // [b,t, fw(z,r,h)|bw(z,r,h)]
__device__ float g_hidden[(size_t)BB * TT * 2 * HH]; // [b,t, fw64|bw64]
// bf16x3 planes of X [131072][256] and combined transposed weights [384][256]
__device__ unsigned short g_Xb0[(size_t)BB * TT * DD];
__device__ unsigned short g_Xb1[(size_t)BB * TT * DD];
__device__ unsigned short g_Xb2[(size_t)BB * TT * DD];
__device__ unsigned short g_Bb0[(size_t)NCOMB * DD];
__device__ unsigned short g_Bb1[(size_t)NCOMB * DD];
__device__ unsigned short g_Bb2[(size_t)NCOMB * DD];

// packed fp32x2 helpers (GRU)
#define FFMA2(acc, a, b) \
    asm("fma.rn.f32x2 %0, %1, %2, %0;" : "+l"(acc) : "l"(a), "l"(b))
#define PACK2(out, lo, hi) \
    asm("mov.b64 %0, {%1, %2};" : "=l"(out) : "r"(__float_as_uint(lo)), "r"(__float_as_uint(hi)))
#define UNPACK2(lo, hi, in) \
    asm("mov.b64 {%0, %1}, %2;" : "=f"(lo), "=f"(hi) : "l"(in))

// bf16 mma m16n8k16 (native HMMA, sm_80+, valid under compute_103)
#define MMA_BF16(c, a, b) \
    asm volatile("mma.sync.aligned.m16n8k16.row.col.f32.bf16.bf16.f32 " \
        "{%0,%1,%2,%3}, {%4,%5,%6,%7}, {%8,%9}, {%0,%1,%2,%3};" \
        : "+f"((c)[0]), "+f"((c)[1]), "+f"((c)[2]), "+f"((c)[3]) \
        : "r"((a)[0]), "r"((a)[1]), "r"((a)[2]), "r"((a)[3]), \
          "r"((b)[0]), "r"((b)[1]))

__device__ __forceinline__ void bf16_split3(float x, unsigned short& h0,
                                            unsigned short& h1, unsigned short& h2)
{
    __nv_bfloat16 b0 = __float2bfloat16(x);
    float f0 = __bfloat162float(b0);
    float r1 = x - f0;
    __nv_bfloat16 b1 = __float2bfloat16(r1);
    float f1 = __bfloat162float(b1);
    __nv_bfloat16 b2 = __float2bfloat16(r1 - f1);
    h0 = __bfloat16_as_ushort(b0);
    h1 = __bfloat16_as_ushort(b1);
    h2 = __bfloat16_as_ushort(b2);
}

// ---------------------------------------------------------------------------
// K0a: split X into 3 bf16 planes (memory-bound)
// ---------------------------------------------------------------------------
__global__ void prep_x(const float* __restrict__ X)
{
    const size_t N4 = (size_t)BB * TT * DD / 4;
    size_t i = (size_t)blockIdx.x * blockDim.x + threadIdx.x;
    size_t stride = (size_t)gridDim.x * blockDim.x;
    for (size_t p = i; p < N4; p += stride) {
        float4 v = ((const float4*)X)[p];
        float xs[4] = {v.x, v.y, v.z, v.w};
        unsigned short h0[4], h1[4], h2[4];
#pragma unroll
        for (int e = 0; e < 4; e++) bf16_split3(xs[e], h0[e], h1[e], h2[e]);
        ((uint2*)g_Xb0)[p] = make_uint2((uint32_t)h0[0] | ((uint32_t)h0[1] << 16),
                                        (uint32_t)h0[2] | ((uint32_t)h0[3] << 16));
        ((uint2*)g_Xb1)[p] = make_uint2((uint32_t)h1[0] | ((uint32_t)h1[1] << 16),
                                        (uint32_t)h1[2] | ((uint32_t)h1[3] << 16));
        ((uint2*)g_Xb2)[p] = make_uint2((uint32_t)h2[0] | ((uint32_t)h2[1] << 16),
                                        (uint32_t)h2[2] | ((uint32_t)h2[3] << 16));
    }
}

// ---------------------------------------------------------------------------
// K0b: transpose + split the combined input weights: g_Bb[n][k]
// ---------------------------------------------------------------------------
__global__ void prep_b(const float* __restrict__ fwK, const float* __restrict__ bwK)
{
    int n = blockIdx.x;     // 0..383
    int k = threadIdx.x;    // 0..255
    float w = (n < GH) ? fwK[(size_t)k * GH + n] : bwK[(size_t)k * GH + (n - GH)];
    unsigned short h0, h1, h2;
    bf16_split3(w, h0, h1, h2);
    g_Bb0[(size_t)n * DD + k] = h0;
    g_Bb1[(size_t)n * DD + k] = h1;
    g_Bb2[(size_t)n * DD + k] = h2;
}

// ---------------------------------------------------------------------------
// K1: proj = X @ Bt^T + bias via bf16x3 mma.sync m16n8k16.
// CTA 128x128, BK=32. 8 warps 2(M)x4(N), warp tile 64x32.
// smem planes use 20-u32 (80B) row pitch -> all fragment LDS conflict-free.
// ---------------------------------------------------------------------------
#define PITCH 20
#define APLANE 2560   // u32 units per plane (128 rows * 20)
#define SM_BIAS 0
#define SM_A 512
#define SM_B (512 + 3 * APLANE * 4)
#define SMEM_PROJ (512 + 6 * APLANE * 4)   // 61952 bytes

__global__ __launch_bounds__(256) void proj_mma(
    const float* __restrict__ fwB, const float* __restrict__ bwB)
{
    extern __shared__ __align__(16) char smem[];
    float* bias_sm = (float*)(smem + SM_BIAS);
    uint32_t* AU = (uint32_t*)(smem + SM_A);
    uint32_t* BU = (uint32_t*)(smem + SM_B);

    const int tid = threadIdx.x;
    const int w = tid >> 5;
    const int lane = tid & 31;
    const int g = lane >> 2;
    const int x = lane & 3;
    const int m_off = (w & 1) * 64;
    const int n_off = (w >> 1) * 32;

    const int n0 = blockIdx.x * 128;   // 0,128,256
    const int m0 = blockIdx.y * 128;

    for (int i = tid; i < 128; i += 256) {
        int n = n0 + i;
        bias_sm[i] = (n < GH) ? fwB[n] : bwB[n - GH];
    }

    float C[4][4][4];
#pragma unroll
    for (int mt = 0; mt < 4; mt++)
#pragma unroll
        for (int nt = 0; nt < 4; nt++)
#pragma unroll
            for (int q = 0; q < 4; q++) C[mt][nt][q] = 0.f;

    int ar0[4], bc0[4];
#pragma unroll
    for (int mt = 0; mt < 4; mt++) ar0[mt] = (m_off + mt * 16 + g) * PITCH;
#pragma unroll
    for (int nt = 0; nt < 4; nt++) bc0[nt] = (n_off + nt * 8 + g) * PITCH;

    const unsigned short* Asrc[3] = {g_Xb0, g_Xb1, g_Xb2};
    const unsigned short* Bsrc[3] = {g_Bb0, g_Bb1, g_Bb2};

    const int crow = tid >> 2;    // 0..63
    const int cq = tid & 3;       // 0..3

    for (int ks = 0; ks < 8; ks++) {
        const int k0 = ks * 32;
        // ---- copy A/B plane slices (uint4, conflict-light)
#pragma unroll
        for (int p = 0; p < 3; p++) {
#pragma unroll
            for (int rep = 0; rep < 2; rep++) {
                int r = crow + rep * 64;
                uint4 va = *(const uint4*)(Asrc[p] + (size_t)(m0 + r) * DD + k0 + cq * 8);
                *(uint4*)(AU + p * APLANE + r * PITCH + cq * 4) = va;
                uint4 vb = *(const uint4*)(Bsrc[p] + (size_t)(n0 + r) * DD + k0 + cq * 8);
                *(uint4*)(BU + p * APLANE + r * PITCH + cq * 4) = vb;
            }
        }
        __syncthreads();

#pragma unroll
        for (int s = 0; s < 2; s++) {
            const int ub = s * 8 + x;
            // B fragments, all 3 planes, held in regs
            uint32_t bf[3][4][2];
#pragma unroll
            for (int p = 0; p < 3; p++)
#pragma unroll
                for (int nt = 0; nt < 4; nt++) {
                    bf[p][nt][0] = BU[p * APLANE + bc0[nt] + ub];
                    bf[p][nt][1] = BU[p * APLANE + bc0[nt] + ub + 4];
                }
            // A plane groups: (pa=0: pb 0..2), (pa=1: pb 0..1), (pa=2: pb 0)
#pragma unroll
            for (int pa = 0; pa < 3; pa++) {
                uint32_t af[4][4];
#pragma unroll
                for (int mt = 0; mt < 4; mt++) {
                    int base = pa * APLANE + ar0[mt] + ub;
                    af[mt][0] = AU[base];
                    af[mt][1] = AU[base + 8 * PITCH];
                    af[mt][2] = AU[base + 4];
                    af[mt][3] = AU[base + 8 * PITCH + 4];
                }
                const int nb = 3 - pa;
#pragma unroll
                for (int pb = 0; pb < 3; pb++) {
                    if (pb >= nb) break;
#pragma unroll
                    for (int mt = 0; mt < 4; mt++)
#pragma unroll
                        for (int nt = 0; nt < 4; nt++)
                            MMA_BF16(C[mt][nt], af[mt], bf[pb][nt]);
                }
            }
        }
        __syncthreads();
    }

    // ---- epilogue: +bias, store
#pragma unroll
    for (int mt = 0; mt < 4; mt++) {
        int r0 = m0 + m_off + mt * 16 + g;
#pragma unroll
        for (int nt = 0; nt < 4; nt++) {
            int col = n_off + nt * 8 + 2 * x;
            float b0 = bias_sm[col], b1 = bias_sm[col + 1];
            float2 v0 = make_float2(C[mt][nt][0] + b0, C[mt][nt][1] + b1);
            float2 v1 = make_float2(C[mt][nt][2] + b0, C[mt][nt][3] + b1);
            *(float2*)(g_xp + (size_t)r0 * NCOMB + n0 + col) = v0;
            *(float2*)(g_xp + (size_t)(r0 + 8) * NCOMB + n0 + col) = v1;
        }
    }
}

// ---------------------------------------------------------------------------
// K2: GRU recurrence (unchanged, known-passing) — 4th launch => ncu target
// ---------------------------------------------------------------------------
__global__ __launch_bounds__(192) void gru_kernel(
    const float* __restrict__ rec_fw, const float* __restrict__ rec_bw,
    const float* __restrict__ bias_fw, const float* __restrict__ bias_bw,
    const int* __restrict__ mask)
{
    __shared__ float h_sm[HH];
    __shared__ float hp_sm[GH];

    int b = blockIdx.x;
    int dir = blockIdx.y;
    int j = threadIdx.x;

    const float* rec = dir ? rec_bw : rec_fw;
    unsigned long long rp[HH / 2];
#pragma unroll
    for (int i = 0; i < HH / 2; i++) {
        float r0 = rec[(2 * i) * GH + j];
        float r1 = rec[(2 * i + 1) * GH + j];
        PACK2(rp[i], r0, r1);
    }
    float brj = (dir ? bias_bw : bias_fw)[GH + j];

    if (j < HH) h_sm[j] = 0.f;
    __syncthreads();

    const int gate = (j < HH);
    float pxz = 0.f, pxr = 0.f, pxh = 0.f;
    int pm = 1;
    if (gate) {
        int tt = dir ? (TT - 1) : 0;
        const float* xr0 = g_xp + ((size_t)b * TT + tt) * NCOMB + dir * GH;
        pxz = xr0[j]; pxr = xr0[HH + j]; pxh = xr0[2 * HH + j];
        pm = mask[b * TT + tt];
    }

    for (int t = 0; t < TT; t++) {
        unsigned long long accA = 0ULL, accB = 0ULL;
        const unsigned long long* h2 = (const unsigned long long*)h_sm;
#pragma unroll
        for (int i = 0; i < HH / 2; i += 2) {
            FFMA2(accA, rp[i], h2[i]);
            FFMA2(accB, rp[i + 1], h2[i + 1]);
        }
        float a0, a1, b0, b1;
        UNPACK2(a0, a1, accA);
        UNPACK2(b0, b1, accB);
        hp_sm[j] = (a0 + a1) + (b0 + b1) + brj;
        __syncthreads();

        if (gate) {
            int tt = dir ? (TT - 1 - t) : t;
            float hz = hp_sm[j];
            float hr = hp_sm[HH + j];
            float hc = hp_sm[2 * HH + j];
            float hprev = h_sm[j];
            float z = 1.f / (1.f + expf(-(pxz + hz)));
            float r = 1.f / (1.f + expf(-(pxr + hr)));
            float c = tanhf(pxh + r * hc);
            float hn = z * hprev + (1.f - z) * c;
            if (pm <= 0) hn = hprev;
            h_sm[j] = hn;
            g_hidden[((size_t)b * TT + tt) * (2 * HH) + dir * HH + j] = hn;
            if (t + 1 < TT) {
                int tn = dir ? (TT - 2 - t) : (t + 1);
                const float* xr = g_xp + ((size_t)b * TT + tn) * NCOMB + dir * GH;
                pxz = xr[j]; pxr = xr[HH + j]; pxh = xr[2 * HH + j];
                pm = mask[b * TT + tn];
            }
        }
        __syncthreads();
    }
}

// ---------------------------------------------------------------------------
// K3: potentials (unchanged)
// ---------------------------------------------------------------------------
__global__ __launch_bounds__(256) void pot_kernel(
    const float* __restrict__ dk, const float* __restrict__ db,
    const float* __restrict__ lb, const float* __restrict__ rb,
    float* __restrict__ pot)
{
    __shared__ float ds[2 * HH * KTAG];
    __shared__ float rows[8][2 * HH];

    int tid = threadIdx.x;
    for (int i = tid; i < 2 * HH * KTAG; i += 256) ds[i] = dk[i];

    int w = tid >> 5, lane = tid & 31;
    size_t row0 = (size_t)blockIdx.x * 8;

    {
        int r = tid >> 5;
        int c4 = (tid & 31) * 4;
        *(float4*)&rows[r][c4] =
            *(const float4*)(g_hidden + (row0 + r) * (2 * HH) + c4);
    }
    __syncthreads();

    float acc = db[lane];
#pragma unroll
    for (int h4 = 0; h4 < 32; h4++) {
        float4 hv = *(const float4*)&rows[w][h4 * 4];
        acc = fmaf(hv.x, ds[(4 * h4 + 0) * KTAG + lane], acc);
        acc = fmaf(hv.y, ds[(4 * h4 + 1) * KTAG + lane], acc);
        acc = fmaf(hv.z, ds[(4 * h4 + 2) * KTAG + lane], acc);
        acc = fmaf(hv.w, ds[(4 * h4 + 3) * KTAG + lane], acc);
    }
    size_t row = row0 + w;
    int t = (int)(row % TT);
    if (t == 0)      acc += lb[lane];
    if (t == TT - 1) acc += rb[lane];
    pot[row * KTAG + lane] = acc;
}

// ---------------------------------------------------------------------------
// K4: Viterbi (unchanged)
// ---------------------------------------------------------------------------
__device__ __forceinline__ void amerge(float& mv, int& mi, float v, int i)
{
    if (v > mv || (v == mv && i < mi)) { mv = v; mi = i; }
}

__global__ __launch_bounds__(32) void viterbi_kernel(
    const float* __restrict__ pot, const float* __restrict__ trans,
    const int* __restrict__ mask,
    float* __restrict__ out_dec, float* __restrict__ out_len)
{
    __shared__ unsigned char bp[TT][KTAG];
    __shared__ unsigned char dec[TT];

    int b = blockIdx.x, k = threadIdx.x;

    float tr[KTAG];
#pragma unroll
    for (int j = 0; j < KTAG; j++) tr[j] = trans[j * KTAG + k];

    const float* pb = pot + (size_t)b * TT * KTAG;
    float s = pb[k];

    for (int t0 = 1; t0 < TT; t0 += 8) {
        float pv[8];
#pragma unroll
        for (int u = 0; u < 8; u++) {
            int t = t0 + u;
            pv[u] = (t < TT) ? pb[(size_t)t * KTAG + k] : 0.f;
        }
#pragma unroll
        for (int u = 0; u < 8; u++) {
            int t = t0 + u;
            if (t >= TT) break;
            float m0 = -INFINITY, m1 = -INFINITY, m2 = -INFINITY, m3 = -INFINITY;
            int i0 = 0, i1 = 1, i2 = 2, i3 = 3;
#pragma unroll
            for (int j = 0; j < KTAG; j += 4) {
                float v0 = __shfl_sync(0xffffffffu, s, j)     + tr[j];
                float v1 = __shfl_sync(0xffffffffu, s, j + 1) + tr[j + 1];
                float v2 = __shfl_sync(0xffffffffu, s, j + 2) + tr[j + 2];
                float v3 = __shfl_sync(0xffffffffu, s, j + 3) + tr[j + 3];
                if (v0 > m0) { m0 = v0; i0 = j; }
                if (v1 > m1) { m1 = v1; i1 = j + 1; }
                if (v2 > m2) { m2 = v2; i2 = j + 2; }
                if (v3 > m3) { m3 = v3; i3 = j + 3; }
            }
            amerge(m0, i0, m1, i1);
            amerge(m2, i2, m3, i3);
            amerge(m0, i0, m2, i2);
            s = m0 + pv[u];
            bp[t][k] = (unsigned char)i0;
        }
    }

    float m0 = -INFINITY, m1 = -INFINITY, m2 = -INFINITY, m3 = -INFINITY;
    int i0 = 0, i1 = 1, i2 = 2, i3 = 3;
#pragma unroll
    for (int j = 0; j < KTAG; j += 4) {
        float v0 = __shfl_sync(0xffffffffu, s, j);
        float v1 = __shfl_sync(0xffffffffu, s, j + 1);
        float v2 = __shfl_sync(0xffffffffu, s, j + 2);
        float v3 = __shfl_sync(0xffffffffu, s, j + 3);
        if (v0 > m0) { m0 = v0; i0 = j; }
        if (v1 > m1) { m1 = v1; i1 = j + 1; }
        if (v2 > m2) { m2 = v2; i2 = j + 2; }
        if (v3 > m3) { m3 = v3; i3 = j + 3; }
    }
    amerge(m0, i0, m1, i1);
    amerge(m2, i2, m3, i3);
    amerge(m0, i0, m2, i2);

    __syncwarp();
    if (k == 0) {
        int tag = i0;
        dec[TT - 1] = (unsigned char)tag;
        for (int t = TT - 2; t >= 0; t--) {
            tag = bp[t + 1][tag];
            dec[t] = (unsigned char)tag;
        }
    }
    __syncwarp();

    for (int t = k; t < TT; t += 32)
        out_dec[(size_t)b * TT + t] = (float)dec[t];

    int sum = 0;
    for (int t = k; t < TT; t += 32) sum += mask[(size_t)b * TT + t];
#pragma unroll
    for (int o = 16; o > 0; o >>= 1) sum += __shfl_down_sync(0xffffffffu, sum, o);
    if (k == 0) out_len[b] = (float)sum;
}

// K5: copy chain_kernel into the output tail
__global__ void tail_kernel(const float* __restrict__ chain, float* __restrict__ outc)
{
    int i = threadIdx.x + blockIdx.x * blockDim.x;
    if (i < KTAG * KTAG) outc[i] = chain[i];
}

// ---------------------------------------------------------------------------
extern "C" void kernel_launch(void* const* d_in, const int* in_sizes, int n_in,
                              void* d_out, int out_size)
{
    const float* X      = (const float*)d_in[0];
    const int*   mask   = (const int*)d_in[1];
    const float* fwK    = (const float*)d_in[2];
    const float* fwR    = (const float*)d_in[3];
    const float* fwBias = (const float*)d_in[4];
    const float* bwK    = (const float*)d_in[5];
    const float* bwR    = (const float*)d_in[6];
    const float* bwBias = (const float*)d_in[7];
    const float* dK     = (const float*)d_in[8];
    const float* dB     = (const float*)d_in[9];
    const float* chain  = (const float*)d_in[10];
    const float* lb     = (const float*)d_in[11];
    const float* rb     = (const float*)d_in[12];

    float* out       = (float*)d_out;
    float* out_dec   = out;                              // B*T
    float* pot       = out + (size_t)BB * TT;            // B*T*K
    float* out_len   = pot + (size_t)BB * TT * KTAG;     // B
    float* out_chain = out_len + BB;                     // K*K

    cudaFuncSetAttribute(proj_mma, cudaFuncAttributeMaxDynamicSharedMemorySize, SMEM_PROJ);

    prep_x<<<2048, 256>>>(X);
    prep_b<<<NCOMB, 256>>>(fwK, bwK);
    dim3 gp(NCOMB / 128, (BB * TT) / 128);
    proj_mma<<<gp, 256, SMEM_PROJ>>>(fwBias, bwBias);
    dim3 g2(BB, 2);
    gru_kernel<<<g2, GH>>>(fwR, bwR, fwBias, bwBias, mask);   // 4th launch -> ncu
    pot_kernel<<<(BB * TT) / 8, 256>>>(dK, dB, lb, rb, pot);
    viterbi_kernel<<<BB, 32>>>(pot, chain, mask, out_dec, out_len);
    tail_kernel<<<4, 256>>>(chain, out_chain);
}

// round 6
// speedup vs baseline: 1.1592x; 1.1396x over previous
#include <cuda_runtime.h>
#include <cuda_bf16.h>
#include <math.h>
#include <cstdint>

#define BB 256
#define TT 512
#define DD 256
#define HH 64
#define KTAG 32
#define GH 192      // 3*H
#define NCOMB 384   // fw 192 | bw 192

// Scratch (allocation-free rule: __device__ globals)
__device__ float g_xp[(size_t)BB * TT * NCOMB];      // [b,t, fw(z,r,h)|bw(z,r,h)]
__device__ float g_hidden[(size_t)BB * TT * 2 * HH]; // [b,t, fw64|bw64]
// bf16x3 planes of X [131072][256] and combined transposed weights [384][256]
__device__ unsigned short g_Xb0[(size_t)BB * TT * DD];
__device__ unsigned short g_Xb1[(size_t)BB * TT * DD];
__device__ unsigned short g_Xb2[(size_t)BB * TT * DD];
__device__ unsigned short g_Bb0[(size_t)NCOMB * DD];
__device__ unsigned short g_Bb1[(size_t)NCOMB * DD];
__device__ unsigned short g_Bb2[(size_t)NCOMB * DD];

// packed fp32x2 helpers (GRU)
#define FFMA2(acc, a, b) \
    asm("fma.rn.f32x2 %0, %1, %2, %0;" : "+l"(acc) : "l"(a), "l"(b))
#define PACK2(out, lo, hi) \
    asm("mov.b64 %0, {%1, %2};" : "=l"(out) : "r"(__float_as_uint(lo)), "r"(__float_as_uint(hi)))
#define UNPACK2(lo, hi, in) \
    asm("mov.b64 {%0, %1}, %2;" : "=f"(lo), "=f"(hi) : "l"(in))

// fast gate math: MUFU ex2/rcp only, no IEEE div, rel err ~1e-6
__device__ __forceinline__ float fast_sigmoid(float x) {
    float e, r;
    asm("ex2.approx.ftz.f32 %0, %1;" : "=f"(e) : "f"(x * -1.4426950408889634f));
    asm("rcp.approx.ftz.f32 %0, %1;" : "=f"(r) : "f"(1.0f + e));
    return r;
}
__device__ __forceinline__ float fast_tanh(float x) {
    float ax = fabsf(x);
    float e, r;
    asm("ex2.approx.ftz.f32 %0, %1;" : "=f"(e) : "f"(ax * -2.8853900817779268f));
    asm("rcp.approx.ftz.f32 %0, %1;" : "=f"(r) : "f"(1.0f + e));
    float t = (1.0f - e) * r;
    return __uint_as_float(__float_as_uint(t) | (__float_as_uint(x) & 0x80000000u));
}

// bf16 mma m16n8k16 (native HMMA, sm_80+, valid under compute_103)
#define MMA_BF16(c, a, b) \
    asm volatile("mma.sync.aligned.m16n8k16.row.col.f32.bf16.bf16.f32 " \
        "{%0,%1,%2,%3}, {%4,%5,%6,%7}, {%8,%9}, {%0,%1,%2,%3};" \
        : "+f"((c)[0]), "+f"((c)[1]), "+f"((c)[2]), "+f"((c)[3]) \
        : "r"((a)[0]), "r"((a)[1]), "r"((a)[2]), "r"((a)[3]), \
          "r"((b)[0]), "r"((b)[1]))

__device__ __forceinline__ void bf16_split3(float x, unsigned short& h0,
                                            unsigned short& h1, unsigned short& h2)
{
    __nv_bfloat16 b0 = __float2bfloat16(x);
    float f0 = __bfloat162float(b0);
    float r1 = x - f0;
    __nv_bfloat16 b1 = __float2bfloat16(r1);
    float f1 = __bfloat162float(b1);
    __nv_bfloat16 b2 = __float2bfloat16(r1 - f1);
    h0 = __bfloat16_as_ushort(b0);
    h1 = __bfloat16_as_ushort(b1);
    h2 = __bfloat16_as_ushort(b2);
}

// ---------------------------------------------------------------------------
// K0a: split X into 3 bf16 planes (memory-bound)
// ---------------------------------------------------------------------------
__global__ void prep_x(const float* __restrict__ X)
{
    const size_t N4 = (size_t)BB * TT * DD / 4;
    size_t i = (size_t)blockIdx.x * blockDim.x + threadIdx.x;
    size_t stride = (size_t)gridDim.x * blockDim.x;
    for (size_t p = i; p < N4; p += stride) {
        float4 v = ((const float4*)X)[p];
        float xs[4] = {v.x, v.y, v.z, v.w};
        unsigned short h0[4], h1[4], h2[4];
#pragma unroll
        for (int e = 0; e < 4; e++) bf16_split3(xs[e], h0[e], h1[e], h2[e]);
        ((uint2*)g_Xb0)[p] = make_uint2((uint32_t)h0[0] | ((uint32_t)h0[1] << 16),
                                        (uint32_t)h0[2] | ((uint32_t)h0[3] << 16));
        ((uint2*)g_Xb1)[p] = make_uint2((uint32_t)h1[0] | ((uint32_t)h1[1] << 16),
                                        (uint32_t)h1[2] | ((uint32_t)h1[3] << 16));
        ((uint2*)g_Xb2)[p] = make_uint2((uint32_t)h2[0] | ((uint32_t)h2[1] << 16),
                                        (uint32_t)h2[2] | ((uint32_t)h2[3] << 16));
    }
}

// ---------------------------------------------------------------------------
// K0b: transpose + split the combined input weights: g_Bb[n][k]
// ---------------------------------------------------------------------------
__global__ void prep_b(const float* __restrict__ fwK, const float* __restrict__ bwK)
{
    int n = blockIdx.x;     // 0..383
    int k = threadIdx.x;    // 0..255
    float w = (n < GH) ? fwK[(size_t)k * GH + n] : bwK[(size_t)k * GH + (n - GH)];
    unsigned short h0, h1, h2;
    bf16_split3(w, h0, h1, h2);
    g_Bb0[(size_t)n * DD + k] = h0;
    g_Bb1[(size_t)n * DD + k] = h1;
    g_Bb2[(size_t)n * DD + k] = h2;
}

// ---------------------------------------------------------------------------
// K1: proj = X @ Bt^T + bias via bf16x3 mma.sync m16n8k16 (unchanged)
// ---------------------------------------------------------------------------
#define PITCH 20
#define APLANE 2560   // u32 units per plane (128 rows * 20)
#define SM_BIAS 0
#define SM_A 512
#define SM_B (512 + 3 * APLANE * 4)
#define SMEM_PROJ (512 + 6 * APLANE * 4)   // 61952 bytes

__global__ __launch_bounds__(256) void proj_mma(
    const float* __restrict__ fwB, const float* __restrict__ bwB)
{
    extern __shared__ __align__(16) char smem[];
    float* bias_sm = (float*)(smem + SM_BIAS);
    uint32_t* AU = (uint32_t*)(smem + SM_A);
    uint32_t* BU = (uint32_t*)(smem + SM_B);

    const int tid = threadIdx.x;
    const int w = tid >> 5;
    const int lane = tid & 31;
    const int g = lane >> 2;
    const int x = lane & 3;
    const int m_off = (w & 1) * 64;
    const int n_off = (w >> 1) * 32;

    const int n0 = blockIdx.x * 128;   // 0,128,256
    const int m0 = blockIdx.y * 128;

    for (int i = tid; i < 128; i += 256) {
        int n = n0 + i;
        bias_sm[i] = (n < GH) ? fwB[n] : bwB[n - GH];
    }

    float C[4][4][4];
#pragma unroll
    for (int mt = 0; mt < 4; mt++)
#pragma unroll
        for (int nt = 0; nt < 4; nt++)
#pragma unroll
            for (int q = 0; q < 4; q++) C[mt][nt][q] = 0.f;

    int ar0[4], bc0[4];
#pragma unroll
    for (int mt = 0; mt < 4; mt++) ar0[mt] = (m_off + mt * 16 + g) * PITCH;
#pragma unroll
    for (int nt = 0; nt < 4; nt++) bc0[nt] = (n_off + nt * 8 + g) * PITCH;

    const unsigned short* Asrc[3] = {g_Xb0, g_Xb1, g_Xb2};
    const unsigned short* Bsrc[3] = {g_Bb0, g_Bb1, g_Bb2};

    const int crow = tid >> 2;    // 0..63
    const int cq = tid & 3;       // 0..3

    for (int ks = 0; ks < 8; ks++) {
        const int k0 = ks * 32;
#pragma unroll
        for (int p = 0; p < 3; p++) {
#pragma unroll
            for (int rep = 0; rep < 2; rep++) {
                int r = crow + rep * 64;
                uint4 va = *(const uint4*)(Asrc[p] + (size_t)(m0 + r) * DD + k0 + cq * 8);
                *(uint4*)(AU + p * APLANE + r * PITCH + cq * 4) = va;
                uint4 vb = *(const uint4*)(Bsrc[p] + (size_t)(n0 + r) * DD + k0 + cq * 8);
                *(uint4*)(BU + p * APLANE + r * PITCH + cq * 4) = vb;
            }
        }
        __syncthreads();

#pragma unroll
        for (int s = 0; s < 2; s++) {
            const int ub = s * 8 + x;
            uint32_t bf[3][4][2];
#pragma unroll
            for (int p = 0; p < 3; p++)
#pragma unroll
                for (int nt = 0; nt < 4; nt++) {
                    bf[p][nt][0] = BU[p * APLANE + bc0[nt] + ub];
                    bf[p][nt][1] = BU[p * APLANE + bc0[nt] + ub + 4];
                }
#pragma unroll
            for (int pa = 0; pa < 3; pa++) {
                uint32_t af[4][4];
#pragma unroll
                for (int mt = 0; mt < 4; mt++) {
                    int base = pa * APLANE + ar0[mt] + ub;
                    af[mt][0] = AU[base];
                    af[mt][1] = AU[base + 8 * PITCH];
                    af[mt][2] = AU[base + 4];
                    af[mt][3] = AU[base + 8 * PITCH + 4];
                }
                const int nb = 3 - pa;
#pragma unroll
                for (int pb = 0; pb < 3; pb++) {
                    if (pb >= nb) break;
#pragma unroll
                    for (int mt = 0; mt < 4; mt++)
#pragma unroll
                        for (int nt = 0; nt < 4; nt++)
                            MMA_BF16(C[mt][nt], af[mt], bf[pb][nt]);
                }
            }
        }
        __syncthreads();
    }

#pragma unroll
    for (int mt = 0; mt < 4; mt++) {
        int r0 = m0 + m_off + mt * 16 + g;
#pragma unroll
        for (int nt = 0; nt < 4; nt++) {
            int col = n_off + nt * 8 + 2 * x;
            float b0 = bias_sm[col], b1 = bias_sm[col + 1];
            float2 v0 = make_float2(C[mt][nt][0] + b0, C[mt][nt][1] + b1);
            float2 v1 = make_float2(C[mt][nt][2] + b0, C[mt][nt][3] + b1);
            *(float2*)(g_xp + (size_t)r0 * NCOMB + n0 + col) = v0;
            *(float2*)(g_xp + (size_t)(r0 + 8) * NCOMB + n0 + col) = v1;
        }
    }
}

// ---------------------------------------------------------------------------
// K2: GRU recurrence. NB=2 batches per block -> 256 blocks (single wave),
// fast MUFU gate math (no IEEE div / libdevice tanh), 4 FFMA2 chains of ILP.
// ---------------------------------------------------------------------------
#define NBAT 2

__global__ __launch_bounds__(192) void gru_kernel(
    const float* __restrict__ rec_fw, const float* __restrict__ rec_bw,
    const float* __restrict__ bias_fw, const float* __restrict__ bias_bw,
    const int* __restrict__ mask)
{
    __shared__ float h_sm[NBAT][HH];
    __shared__ float hp_sm[NBAT][GH];

    const int dir = blockIdx.y;
    const int b0 = blockIdx.x * NBAT;
    const int j = threadIdx.x;

    const float* rec = dir ? rec_bw : rec_fw;
    unsigned long long rp[HH / 2];
#pragma unroll
    for (int i = 0; i < HH / 2; i++) {
        float r0 = rec[(2 * i) * GH + j];
        float r1 = rec[(2 * i + 1) * GH + j];
        PACK2(rp[i], r0, r1);
    }
    const float brj = (dir ? bias_bw : bias_fw)[GH + j];

    if (j < HH) {
#pragma unroll
        for (int nb = 0; nb < NBAT; nb++) h_sm[nb][j] = 0.f;
    }
    __syncthreads();

    const int gate = (j < HH);
    float pxz[NBAT], pxr[NBAT], pxh[NBAT];
    int pm[NBAT];
    if (gate) {
        int tt = dir ? (TT - 1) : 0;
#pragma unroll
        for (int nb = 0; nb < NBAT; nb++) {
            const float* xr0 = g_xp + ((size_t)(b0 + nb) * TT + tt) * NCOMB + dir * GH;
            pxz[nb] = xr0[j]; pxr[nb] = xr0[HH + j]; pxh[nb] = xr0[2 * HH + j];
            pm[nb] = mask[(b0 + nb) * TT + tt];
        }
    }

    for (int t = 0; t < TT; t++) {
        // 4 independent FFMA2 chains (2 per batch)
        unsigned long long a00 = 0ULL, a01 = 0ULL, a10 = 0ULL, a11 = 0ULL;
        const unsigned long long* h20 = (const unsigned long long*)h_sm[0];
        const unsigned long long* h21 = (const unsigned long long*)h_sm[1];
#pragma unroll
        for (int i = 0; i < HH / 2; i += 2) {
            FFMA2(a00, rp[i],     h20[i]);
            FFMA2(a01, rp[i + 1], h20[i + 1]);
            FFMA2(a10, rp[i],     h21[i]);
            FFMA2(a11, rp[i + 1], h21[i + 1]);
        }
        {
            float x0, x1, y0, y1;
            UNPACK2(x0, x1, a00); UNPACK2(y0, y1, a01);
            hp_sm[0][j] = (x0 + x1) + (y0 + y1) + brj;
            UNPACK2(x0, x1, a10); UNPACK2(y0, y1, a11);
            hp_sm[1][j] = (x0 + x1) + (y0 + y1) + brj;
        }
        __syncthreads();

        if (gate) {
            const int tt = dir ? (TT - 1 - t) : t;
#pragma unroll
            for (int nb = 0; nb < NBAT; nb++) {
                float hz = hp_sm[nb][j];
                float hr = hp_sm[nb][HH + j];
                float hc = hp_sm[nb][2 * HH + j];
                float hprev = h_sm[nb][j];
                float z = fast_sigmoid(pxz[nb] + hz);
                float r = fast_sigmoid(pxr[nb] + hr);
                float c = fast_tanh(pxh[nb] + r * hc);
                float hn = z * hprev + (1.f - z) * c;
                if (pm[nb] <= 0) hn = hprev;
                h_sm[nb][j] = hn;
                g_hidden[((size_t)(b0 + nb) * TT + tt) * (2 * HH) + dir * HH + j] = hn;
            }
            if (t + 1 < TT) {
                const int tn = dir ? (TT - 2 - t) : (t + 1);
#pragma unroll
                for (int nb = 0; nb < NBAT; nb++) {
                    const float* xr = g_xp + ((size_t)(b0 + nb) * TT + tn) * NCOMB + dir * GH;
                    pxz[nb] = xr[j]; pxr[nb] = xr[HH + j]; pxh[nb] = xr[2 * HH + j];
                    pm[nb] = mask[(b0 + nb) * TT + tn];
                }
            }
        }
        __syncthreads();
    }
}

// ---------------------------------------------------------------------------
// K3: potentials (unchanged)
// ---------------------------------------------------------------------------
__global__ __launch_bounds__(256) void pot_kernel(
    const float* __restrict__ dk, const float* __restrict__ db,
    const float* __restrict__ lb, const float* __restrict__ rb,
    float* __restrict__ pot)
{
    __shared__ float ds[2 * HH * KTAG];
    __shared__ float rows[8][2 * HH];

    int tid = threadIdx.x;
    for (int i = tid; i < 2 * HH * KTAG; i += 256) ds[i] = dk[i];

    int w = tid >> 5, lane = tid & 31;
    size_t row0 = (size_t)blockIdx.x * 8;

    {
        int r = tid >> 5;
        int c4 = (tid & 31) * 4;
        *(float4*)&rows[r][c4] =
            *(const float4*)(g_hidden + (row0 + r) * (2 * HH) + c4);
    }
    __syncthreads();

    float acc = db[lane];
#pragma unroll
    for (int h4 = 0; h4 < 32; h4++) {
        float4 hv = *(const float4*)&rows[w][h4 * 4];
        acc = fmaf(hv.x, ds[(4 * h4 + 0) * KTAG + lane], acc);
        acc = fmaf(hv.y, ds[(4 * h4 + 1) * KTAG + lane], acc);
        acc = fmaf(hv.z, ds[(4 * h4 + 2) * KTAG + lane], acc);
        acc = fmaf(hv.w, ds[(4 * h4 + 3) * KTAG + lane], acc);
    }
    size_t row = row0 + w;
    int t = (int)(row % TT);
    if (t == 0)      acc += lb[lane];
    if (t == TT - 1) acc += rb[lane];
    pot[row * KTAG + lane] = acc;
}

// ---------------------------------------------------------------------------
// K4: Viterbi (unchanged)
// ---------------------------------------------------------------------------
__device__ __forceinline__ void amerge(float& mv, int& mi, float v, int i)
{
    if (v > mv || (v == mv && i < mi)) { mv = v; mi = i; }
}

__global__ __launch_bounds__(32) void viterbi_kernel(
    const float* __restrict__ pot, const float* __restrict__ trans,
    const int* __restrict__ mask,
    float* __restrict__ out_dec, float* __restrict__ out_len)
{
    __shared__ unsigned char bp[TT][KTAG];
    __shared__ unsigned char dec[TT];

    int b = blockIdx.x, k = threadIdx.x;

    float tr[KTAG];
#pragma unroll
    for (int j = 0; j < KTAG; j++) tr[j] = trans[j * KTAG + k];

    const float* pb = pot + (size_t)b * TT * KTAG;
    float s = pb[k];

    for (int t0 = 1; t0 < TT; t0 += 8) {
        float pv[8];
#pragma unroll
        for (int u = 0; u < 8; u++) {
            int t = t0 + u;
            pv[u] = (t < TT) ? pb[(size_t)t * KTAG + k] : 0.f;
        }
#pragma unroll
        for (int u = 0; u < 8; u++) {
            int t = t0 + u;
            if (t >= TT) break;
            float m0 = -INFINITY, m1 = -INFINITY, m2 = -INFINITY, m3 = -INFINITY;
            int i0 = 0, i1 = 1, i2 = 2, i3 = 3;
#pragma unroll
            for (int j = 0; j < KTAG; j += 4) {
                float v0 = __shfl_sync(0xffffffffu, s, j)     + tr[j];
                float v1 = __shfl_sync(0xffffffffu, s, j + 1) + tr[j + 1];
                float v2 = __shfl_sync(0xffffffffu, s, j + 2) + tr[j + 2];
                float v3 = __shfl_sync(0xffffffffu, s, j + 3) + tr[j + 3];
                if (v0 > m0) { m0 = v0; i0 = j; }
                if (v1 > m1) { m1 = v1; i1 = j + 1; }
                if (v2 > m2) { m2 = v2; i2 = j + 2; }
                if (v3 > m3) { m3 = v3; i3 = j + 3; }
            }
            amerge(m0, i0, m1, i1);
            amerge(m2, i2, m3, i3);
            amerge(m0, i0, m2, i2);
            s = m0 + pv[u];
            bp[t][k] = (unsigned char)i0;
        }
    }

    float m0 = -INFINITY, m1 = -INFINITY, m2 = -INFINITY, m3 = -INFINITY;
    int i0 = 0, i1 = 1, i2 = 2, i3 = 3;
#pragma unroll
    for (int j = 0; j < KTAG; j += 4) {
        float v0 = __shfl_sync(0xffffffffu, s, j);
        float v1 = __shfl_sync(0xffffffffu, s, j + 1);
        float v2 = __shfl_sync(0xffffffffu, s, j + 2);
        float v3 = __shfl_sync(0xffffffffu, s, j + 3);
        if (v0 > m0) { m0 = v0; i0 = j; }
        if (v1 > m1) { m1 = v1; i1 = j + 1; }
        if (v2 > m2) { m2 = v2; i2 = j + 2; }
        if (v3 > m3) { m3 = v3; i3 = j + 3; }
    }
    amerge(m0, i0, m1, i1);
    amerge(m2, i2, m3, i3);
    amerge(m0, i0, m2, i2);

    __syncwarp();
    if (k == 0) {
        int tag = i0;
        dec[TT - 1] = (unsigned char)tag;
        for (int t = TT - 2; t >= 0; t--) {
            tag = bp[t + 1][tag];
            dec[t] = (unsigned char)tag;
        }
    }
    __syncwarp();

    for (int t = k; t < TT; t += 32)
        out_dec[(size_t)b * TT + t] = (float)dec[t];

    int sum = 0;
    for (int t = k; t < TT; t += 32) sum += mask[(size_t)b * TT + t];
#pragma unroll
    for (int o = 16; o > 0; o >>= 1) sum += __shfl_down_sync(0xffffffffu, sum, o);
    if (k == 0) out_len[b] = (float)sum;
}

// K5: copy chain_kernel into the output tail
__global__ void tail_kernel(const float* __restrict__ chain, float* __restrict__ outc)
{
    int i = threadIdx.x + blockIdx.x * blockDim.x;
    if (i < KTAG * KTAG) outc[i] = chain[i];
}

// ---------------------------------------------------------------------------
extern "C" void kernel_launch(void* const* d_in, const int* in_sizes, int n_in,
                              void* d_out, int out_size)
{
    const float* X      = (const float*)d_in[0];
    const int*   mask   = (const int*)d_in[1];
    const float* fwK    = (const float*)d_in[2];
    const float* fwR    = (const float*)d_in[3];
    const float* fwBias = (const float*)d_in[4];
    const float* bwK    = (const float*)d_in[5];
    const float* bwR    = (const float*)d_in[6];
    const float* bwBias = (const float*)d_in[7];
    const float* dK     = (const float*)d_in[8];
    const float* dB     = (const float*)d_in[9];
    const float* chain  = (const float*)d_in[10];
    const float* lb     = (const float*)d_in[11];
    const float* rb     = (const float*)d_in[12];

    float* out       = (float*)d_out;
    float* out_dec   = out;                              // B*T
    float* pot       = out + (size_t)BB * TT;            // B*T*K
    float* out_len   = pot + (size_t)BB * TT * KTAG;     // B
    float* out_chain = out_len + BB;                     // K*K

    cudaFuncSetAttribute(proj_mma, cudaFuncAttributeMaxDynamicSharedMemorySize, SMEM_PROJ);

    prep_x<<<2048, 256>>>(X);
    prep_b<<<NCOMB, 256>>>(fwK, bwK);
    dim3 gp(NCOMB / 128, (BB * TT) / 128);
    proj_mma<<<gp, 256, SMEM_PROJ>>>(fwBias, bwBias);
    dim3 g2(BB / NBAT, 2);
    gru_kernel<<<g2, GH>>>(fwR, bwR, fwBias, bwBias, mask);   // 4th launch -> ncu
    pot_kernel<<<(BB * TT) / 8, 256>>>(dK, dB, lb, rb, pot);
    viterbi_kernel<<<BB, 32>>>(pot, chain, mask, out_dec, out_len);
    tail_kernel<<<4, 256>>>(chain, out_chain);
}

// round 7
// speedup vs baseline: 1.5903x; 1.3719x over previous
#include <cuda_runtime.h>
#include <cuda_fp16.h>
#include <math.h>
#include <cstdint>

#define BB 256
#define TT 512
#define DD 256
#define HH 64
#define KTAG 32
#define GH 192      // 3*H
#define NCOMB 384   // fw 192 | bw 192

// Scratch (allocation-free rule: __device__ globals)
__device__ float g_xp[(size_t)BB * TT * NCOMB];      // [b,t, fw(z,r,h)|bw(z,r,h)]
__device__ float g_hidden[(size_t)BB * TT * 2 * HH]; // [b,t, fw64|bw64]
// fp16x2 planes of X [131072][256] and combined transposed weights [384][256]
__device__ unsigned short g_Xh0[(size_t)BB * TT * DD];
__device__ unsigned short g_Xh1[(size_t)BB * TT * DD];
__device__ unsigned short g_Bh0[(size_t)NCOMB * DD];
__device__ unsigned short g_Bh1[(size_t)NCOMB * DD];

// packed fp32x2 helpers (GRU)
#define FFMA2(acc, a, b) \
    asm("fma.rn.f32x2 %0, %1, %2, %0;" : "+l"(acc) : "l"(a), "l"(b))
#define PACK2(out, lo, hi) \
    asm("mov.b64 %0, {%1, %2};" : "=l"(out) : "r"(__float_as_uint(lo)), "r"(__float_as_uint(hi)))
#define UNPACK2(lo, hi, in) \
    asm("mov.b64 {%0, %1}, %2;" : "=f"(lo), "=f"(hi) : "l"(in))

// fast gate math: MUFU ex2/rcp only, no IEEE div, rel err ~1e-6
__device__ __forceinline__ float fast_sigmoid(float x) {
    float e, r;
    asm("ex2.approx.ftz.f32 %0, %1;" : "=f"(e) : "f"(x * -1.4426950408889634f));
    asm("rcp.approx.ftz.f32 %0, %1;" : "=f"(r) : "f"(1.0f + e));
    return r;
}
__device__ __forceinline__ float fast_tanh(float x) {
    float ax = fabsf(x);
    float e, r;
    asm("ex2.approx.ftz.f32 %0, %1;" : "=f"(e) : "f"(ax * -2.8853900817779268f));
    asm("rcp.approx.ftz.f32 %0, %1;" : "=f"(r) : "f"(1.0f + e));
    float t = (1.0f - e) * r;
    return __uint_as_float(__float_as_uint(t) | (__float_as_uint(x) & 0x80000000u));
}

// fp16 mma m16n8k16 (native HMMA, sm_80+, valid under compute_103)
#define MMA_F16(c, a, b) \
    asm volatile("mma.sync.aligned.m16n8k16.row.col.f32.f16.f16.f32 " \
        "{%0,%1,%2,%3}, {%4,%5,%6,%7}, {%8,%9}, {%0,%1,%2,%3};" \
        : "+f"((c)[0]), "+f"((c)[1]), "+f"((c)[2]), "+f"((c)[3]) \
        : "r"((a)[0]), "r"((a)[1]), "r"((a)[2]), "r"((a)[3]), \
          "r"((b)[0]), "r"((b)[1]))

__device__ __forceinline__ void fp16_split2(float x, unsigned short& h0, unsigned short& h1)
{
    __half a = __float2half_rn(x);
    float f0 = __half2float(a);
    __half b = __float2half_rn(x - f0);
    h0 = __half_as_ushort(a);
    h1 = __half_as_ushort(b);
}

// ---------------------------------------------------------------------------
// K0a: split X into 2 fp16 planes (memory-bound)
// ---------------------------------------------------------------------------
__global__ void prep_x(const float* __restrict__ X)
{
    const size_t N4 = (size_t)BB * TT * DD / 4;
    size_t i = (size_t)blockIdx.x * blockDim.x + threadIdx.x;
    size_t stride = (size_t)gridDim.x * blockDim.x;
    for (size_t p = i; p < N4; p += stride) {
        float4 v = ((const float4*)X)[p];
        float xs[4] = {v.x, v.y, v.z, v.w};
        unsigned short h0[4], h1[4];
#pragma unroll
        for (int e = 0; e < 4; e++) fp16_split2(xs[e], h0[e], h1[e]);
        ((uint2*)g_Xh0)[p] = make_uint2((uint32_t)h0[0] | ((uint32_t)h0[1] << 16),
                                        (uint32_t)h0[2] | ((uint32_t)h0[3] << 16));
        ((uint2*)g_Xh1)[p] = make_uint2((uint32_t)h1[0] | ((uint32_t)h1[1] << 16),
                                        (uint32_t)h1[2] | ((uint32_t)h1[3] << 16));
    }
}

// ---------------------------------------------------------------------------
// K0b: transpose + split the combined input weights: g_Bh[n][k]
// ---------------------------------------------------------------------------
__global__ void prep_b(const float* __restrict__ fwK, const float* __restrict__ bwK)
{
    int n = blockIdx.x;     // 0..383
    int k = threadIdx.x;    // 0..255
    float w = (n < GH) ? fwK[(size_t)k * GH + n] : bwK[(size_t)k * GH + (n - GH)];
    unsigned short h0, h1;
    fp16_split2(w, h0, h1);
    g_Bh0[(size_t)n * DD + k] = h0;
    g_Bh1[(size_t)n * DD + k] = h1;
}

// ---------------------------------------------------------------------------
// K1: proj = X @ Bt^T + bias via fp16x2 3-product mma.sync m16n8k16.
// CTA 128x128, BK=32. 8 warps 2(M)x4(N), warp tile 64x32.
// smem planes use 20-u32 (80B) row pitch -> all fragment LDS conflict-free.
// ---------------------------------------------------------------------------
#define PITCH 20
#define APLANE 2560   // u32 units per plane (128 rows * 20)
#define SM_BIAS 0
#define SM_A 512
#define SM_B (512 + 2 * APLANE * 4)
#define SMEM_PROJ (512 + 4 * APLANE * 4)   // 41472 bytes

__global__ __launch_bounds__(256) void proj_mma(
    const float* __restrict__ fwB, const float* __restrict__ bwB)
{
    extern __shared__ __align__(16) char smem[];
    float* bias_sm = (float*)(smem + SM_BIAS);
    uint32_t* AU = (uint32_t*)(smem + SM_A);
    uint32_t* BU = (uint32_t*)(smem + SM_B);

    const int tid = threadIdx.x;
    const int w = tid >> 5;
    const int lane = tid & 31;
    const int g = lane >> 2;
    const int x = lane & 3;
    const int m_off = (w & 1) * 64;
    const int n_off = (w >> 1) * 32;

    const int n0 = blockIdx.x * 128;   // 0,128,256
    const int m0 = blockIdx.y * 128;

    for (int i = tid; i < 128; i += 256) {
        int n = n0 + i;
        bias_sm[i] = (n < GH) ? fwB[n] : bwB[n - GH];
    }

    float C[4][4][4];
#pragma unroll
    for (int mt = 0; mt < 4; mt++)
#pragma unroll
        for (int nt = 0; nt < 4; nt++)
#pragma unroll
            for (int q = 0; q < 4; q++) C[mt][nt][q] = 0.f;

    int ar0[4], bc0[4];
#pragma unroll
    for (int mt = 0; mt < 4; mt++) ar0[mt] = (m_off + mt * 16 + g) * PITCH;
#pragma unroll
    for (int nt = 0; nt < 4; nt++) bc0[nt] = (n_off + nt * 8 + g) * PITCH;

    const unsigned short* Asrc[2] = {g_Xh0, g_Xh1};
    const unsigned short* Bsrc[2] = {g_Bh0, g_Bh1};

    const int crow = tid >> 2;    // 0..63
    const int cq = tid & 3;       // 0..3

    for (int ks = 0; ks < 8; ks++) {
        const int k0 = ks * 32;
#pragma unroll
        for (int p = 0; p < 2; p++) {
#pragma unroll
            for (int rep = 0; rep < 2; rep++) {
                int r = crow + rep * 64;
                uint4 va = *(const uint4*)(Asrc[p] + (size_t)(m0 + r) * DD + k0 + cq * 8);
                *(uint4*)(AU + p * APLANE + r * PITCH + cq * 4) = va;
                uint4 vb = *(const uint4*)(Bsrc[p] + (size_t)(n0 + r) * DD + k0 + cq * 8);
                *(uint4*)(BU + p * APLANE + r * PITCH + cq * 4) = vb;
            }
        }
        __syncthreads();

#pragma unroll
        for (int s = 0; s < 2; s++) {
            const int ub = s * 8 + x;
            uint32_t bf[2][4][2];
#pragma unroll
            for (int p = 0; p < 2; p++)
#pragma unroll
                for (int nt = 0; nt < 4; nt++) {
                    bf[p][nt][0] = BU[p * APLANE + bc0[nt] + ub];
                    bf[p][nt][1] = BU[p * APLANE + bc0[nt] + ub + 4];
                }
            // products: a0*b0, a0*b1, a1*b0  (missing a1*b1 ~ 2^-24)
#pragma unroll
            for (int pa = 0; pa < 2; pa++) {
                uint32_t af[4][4];
#pragma unroll
                for (int mt = 0; mt < 4; mt++) {
                    int base = pa * APLANE + ar0[mt] + ub;
                    af[mt][0] = AU[base];
                    af[mt][1] = AU[base + 8 * PITCH];
                    af[mt][2] = AU[base + 4];
                    af[mt][3] = AU[base + 8 * PITCH + 4];
                }
                const int nbp = 2 - pa;   // pa=0 -> b0,b1 ; pa=1 -> b0
#pragma unroll
                for (int pb = 0; pb < 2; pb++) {
                    if (pb >= nbp) break;
#pragma unroll
                    for (int mt = 0; mt < 4; mt++)
#pragma unroll
                        for (int nt = 0; nt < 4; nt++)
                            MMA_F16(C[mt][nt], af[mt], bf[pb][nt]);
                }
            }
        }
        __syncthreads();
    }

#pragma unroll
    for (int mt = 0; mt < 4; mt++) {
        int r0 = m0 + m_off + mt * 16 + g;
#pragma unroll
        for (int nt = 0; nt < 4; nt++) {
            int col = n_off + nt * 8 + 2 * x;
            float b0 = bias_sm[col], b1 = bias_sm[col + 1];
            float2 v0 = make_float2(C[mt][nt][0] + b0, C[mt][nt][1] + b1);
            float2 v1 = make_float2(C[mt][nt][2] + b0, C[mt][nt][3] + b1);
            *(float2*)(g_xp + (size_t)r0 * NCOMB + n0 + col) = v0;
            *(float2*)(g_xp + (size_t)(r0 + 8) * NCOMB + n0 + col) = v1;
        }
    }
}

// ---------------------------------------------------------------------------
// K2: GRU recurrence with warp-specialized deep prefetch.
// Threads 0..63: gate consumers. Threads 64..191: xp producers (3-stage
// register pipeline: LDG for t+6, STS to 4-slot smem ring at t+3), so DRAM
// latency never sits on the barrier path. All 192 threads do the matvec.
// ---------------------------------------------------------------------------
#define NBAT 2
#define RS 4

__global__ __launch_bounds__(192) void gru_kernel(
    const float* __restrict__ rec_fw, const float* __restrict__ rec_bw,
    const float* __restrict__ bias_fw, const float* __restrict__ bias_bw,
    const int* __restrict__ mask)
{
    __shared__ float h_sm[NBAT][HH];
    __shared__ float hp_sm[NBAT][GH];
    __shared__ float ring[RS][NBAT][3][HH];
    __shared__ int ringm[RS][NBAT];

    const int dir = blockIdx.y;
    const int b0 = blockIdx.x * NBAT;
    const int j = threadIdx.x;

    const float* rec = dir ? rec_bw : rec_fw;
    unsigned long long rp[HH / 2];
#pragma unroll
    for (int i = 0; i < HH / 2; i++) {
        float r0 = rec[(2 * i) * GH + j];
        float r1 = rec[(2 * i + 1) * GH + j];
        PACK2(rp[i], r0, r1);
    }
    const float brj = (dir ? bias_bw : bias_fw)[GH + j];

    if (j < HH) {
#pragma unroll
        for (int nb = 0; nb < NBAT; nb++) h_sm[nb][j] = 0.f;
    }

    // producer identity (threads 64..191)
    const int pid = j - HH;          // 0..127 when producer
    const int pnb = (pid >> 6) & 1;  // batch 0/1
    const int pjj = pid & 63;

#define LDXP(TF, Z, R, H, M) do { \
        int _ttf = dir ? (TT - 1 - (TF)) : (TF); \
        const float* _xr = g_xp + ((size_t)(b0 + pnb) * TT + _ttf) * NCOMB + dir * GH; \
        Z = _xr[pjj]; R = _xr[HH + pjj]; H = _xr[2 * HH + pjj]; \
        M = mask[(b0 + pnb) * TT + _ttf]; \
    } while (0)

    float s0z = 0, s0r = 0, s0h = 0, s1z = 0, s1r = 0, s1h = 0, s2z = 0, s2r = 0, s2h = 0;
    int s0m = 1, s1m = 1, s2m = 1;

    if (j >= HH) {
        // prefill ring slots 0..2 (steps 0..2)
        for (int f = 0; f < 3; f++) {
            float z, r, h; int m;
            LDXP(f, z, r, h, m);
            ring[f][pnb][0][pjj] = z;
            ring[f][pnb][1][pjj] = r;
            ring[f][pnb][2][pjj] = h;
            if (pjj == 0) ringm[f][pnb] = m;
        }
        LDXP(3, s0z, s0r, s0h, s0m);
        LDXP(4, s1z, s1r, s1h, s1m);
        LDXP(5, s2z, s2r, s2h, s2m);
    }
    __syncthreads();

    int sr = 0;   // consumer slot (step t)
    int sw = 3;   // producer STS slot (step t+3)

    for (int t = 0; t < TT; t++) {
        // matvec: all 192 threads
        unsigned long long a00 = 0ULL, a01 = 0ULL, a10 = 0ULL, a11 = 0ULL;
        const unsigned long long* h20 = (const unsigned long long*)h_sm[0];
        const unsigned long long* h21 = (const unsigned long long*)h_sm[1];
#pragma unroll
        for (int i = 0; i < HH / 2; i += 2) {
            FFMA2(a00, rp[i],     h20[i]);
            FFMA2(a01, rp[i + 1], h20[i + 1]);
            FFMA2(a10, rp[i],     h21[i]);
            FFMA2(a11, rp[i + 1], h21[i + 1]);
        }
        {
            float x0, x1, y0, y1;
            UNPACK2(x0, x1, a00); UNPACK2(y0, y1, a01);
            hp_sm[0][j] = (x0 + x1) + (y0 + y1) + brj;
            UNPACK2(x0, x1, a10); UNPACK2(y0, y1, a11);
            hp_sm[1][j] = (x0 + x1) + (y0 + y1) + brj;
        }
        __syncthreads();

        if (j < HH) {
            // gate consumers
            const int tt = dir ? (TT - 1 - t) : t;
#pragma unroll
            for (int nb = 0; nb < NBAT; nb++) {
                float xz = ring[sr][nb][0][j];
                float xr_ = ring[sr][nb][1][j];
                float xh = ring[sr][nb][2][j];
                int m = ringm[sr][nb];
                float hz = hp_sm[nb][j];
                float hr = hp_sm[nb][HH + j];
                float hc = hp_sm[nb][2 * HH + j];
                float hprev = h_sm[nb][j];
                float z = fast_sigmoid(xz + hz);
                float r = fast_sigmoid(xr_ + hr);
                float c = fast_tanh(xh + r * hc);
                float hn = z * hprev + (1.f - z) * c;
                if (m <= 0) hn = hprev;
                h_sm[nb][j] = hn;
                g_hidden[((size_t)(b0 + nb) * TT + tt) * (2 * HH) + dir * HH + j] = hn;
            }
        } else {
            // producers: STS stage0 (loaded 3 steps ago) for step t+3, shift, LDG t+6
            const int tf = t + 3;
            if (tf < TT) {
                ring[sw][pnb][0][pjj] = s0z;
                ring[sw][pnb][1][pjj] = s0r;
                ring[sw][pnb][2][pjj] = s0h;
                if (pjj == 0) ringm[sw][pnb] = s0m;
            }
            s0z = s1z; s0r = s1r; s0h = s1h; s0m = s1m;
            s1z = s2z; s1r = s2r; s1h = s2h; s1m = s2m;
            const int tl = t + 6;
            if (tl < TT) LDXP(tl, s2z, s2r, s2h, s2m);
        }
        __syncthreads();

        sr++; if (sr == RS) sr = 0;
        sw++; if (sw == RS) sw = 0;
    }
#undef LDXP
}

// ---------------------------------------------------------------------------
// K3: potentials (unchanged)
// ---------------------------------------------------------------------------
__global__ __launch_bounds__(256) void pot_kernel(
    const float* __restrict__ dk, const float* __restrict__ db,
    const float* __restrict__ lb, const float* __restrict__ rb,
    float* __restrict__ pot)
{
    __shared__ float ds[2 * HH * KTAG];
    __shared__ float rows[8][2 * HH];

    int tid = threadIdx.x;
    for (int i = tid; i < 2 * HH * KTAG; i += 256) ds[i] = dk[i];

    int w = tid >> 5, lane = tid & 31;
    size_t row0 = (size_t)blockIdx.x * 8;

    {
        int r = tid >> 5;
        int c4 = (tid & 31) * 4;
        *(float4*)&rows[r][c4] =
            *(const float4*)(g_hidden + (row0 + r) * (2 * HH) + c4);
    }
    __syncthreads();

    float acc = db[lane];
#pragma unroll
    for (int h4 = 0; h4 < 32; h4++) {
        float4 hv = *(const float4*)&rows[w][h4 * 4];
        acc = fmaf(hv.x, ds[(4 * h4 + 0) * KTAG + lane], acc);
        acc = fmaf(hv.y, ds[(4 * h4 + 1) * KTAG + lane], acc);
        acc = fmaf(hv.z, ds[(4 * h4 + 2) * KTAG + lane], acc);
        acc = fmaf(hv.w, ds[(4 * h4 + 3) * KTAG + lane], acc);
    }
    size_t row = row0 + w;
    int t = (int)(row % TT);
    if (t == 0)      acc += lb[lane];
    if (t == TT - 1) acc += rb[lane];
    pot[row * KTAG + lane] = acc;
}

// ---------------------------------------------------------------------------
// K4: Viterbi (unchanged)
// ---------------------------------------------------------------------------
__device__ __forceinline__ void amerge(float& mv, int& mi, float v, int i)
{
    if (v > mv || (v == mv && i < mi)) { mv = v; mi = i; }
}

__global__ __launch_bounds__(32) void viterbi_kernel(
    const float* __restrict__ pot, const float* __restrict__ trans,
    const int* __restrict__ mask,
    float* __restrict__ out_dec, float* __restrict__ out_len)
{
    __shared__ unsigned char bp[TT][KTAG];
    __shared__ unsigned char dec[TT];

    int b = blockIdx.x, k = threadIdx.x;

    float tr[KTAG];
#pragma unroll
    for (int j = 0; j < KTAG; j++) tr[j] = trans[j * KTAG + k];

    const float* pb = pot + (size_t)b * TT * KTAG;
    float s = pb[k];

    for (int t0 = 1; t0 < TT; t0 += 8) {
        float pv[8];
#pragma unroll
        for (int u = 0; u < 8; u++) {
            int t = t0 + u;
            pv[u] = (t < TT) ? pb[(size_t)t * KTAG + k] : 0.f;
        }
#pragma unroll
        for (int u = 0; u < 8; u++) {
            int t = t0 + u;
            if (t >= TT) break;
            float m0 = -INFINITY, m1 = -INFINITY, m2 = -INFINITY, m3 = -INFINITY;
            int i0 = 0, i1 = 1, i2 = 2, i3 = 3;
#pragma unroll
            for (int j = 0; j < KTAG; j += 4) {
                float v0 = __shfl_sync(0xffffffffu, s, j)     + tr[j];
                float v1 = __shfl_sync(0xffffffffu, s, j + 1) + tr[j + 1];
                float v2 = __shfl_sync(0xffffffffu, s, j + 2) + tr[j + 2];
                float v3 = __shfl_sync(0xffffffffu, s, j + 3) + tr[j + 3];
                if (v0 > m0) { m0 = v0; i0 = j; }
                if (v1 > m1) { m1 = v1; i1 = j + 1; }
                if (v2 > m2) { m2 = v2; i2 = j + 2; }
                if (v3 > m3) { m3 = v3; i3 = j + 3; }
            }
            amerge(m0, i0, m1, i1);
            amerge(m2, i2, m3, i3);
            amerge(m0, i0, m2, i2);
            s = m0 + pv[u];
            bp[t][k] = (unsigned char)i0;
        }
    }

    float m0 = -INFINITY, m1 = -INFINITY, m2 = -INFINITY, m3 = -INFINITY;
    int i0 = 0, i1 = 1, i2 = 2, i3 = 3;
#pragma unroll
    for (int j = 0; j < KTAG; j += 4) {
        float v0 = __shfl_sync(0xffffffffu, s, j);
        float v1 = __shfl_sync(0xffffffffu, s, j + 1);
        float v2 = __shfl_sync(0xffffffffu, s, j + 2);
        float v3 = __shfl_sync(0xffffffffu, s, j + 3);
        if (v0 > m0) { m0 = v0; i0 = j; }
        if (v1 > m1) { m1 = v1; i1 = j + 1; }
        if (v2 > m2) { m2 = v2; i2 = j + 2; }
        if (v3 > m3) { m3 = v3; i3 = j + 3; }
    }
    amerge(m0, i0, m1, i1);
    amerge(m2, i2, m3, i3);
    amerge(m0, i0, m2, i2);

    __syncwarp();
    if (k == 0) {
        int tag = i0;
        dec[TT - 1] = (unsigned char)tag;
        for (int t = TT - 2; t >= 0; t--) {
            tag = bp[t + 1][tag];
            dec[t] = (unsigned char)tag;
        }
    }
    __syncwarp();

    for (int t = k; t < TT; t += 32)
        out_dec[(size_t)b * TT + t] = (float)dec[t];

    int sum = 0;
    for (int t = k; t < TT; t += 32) sum += mask[(size_t)b * TT + t];
#pragma unroll
    for (int o = 16; o > 0; o >>= 1) sum += __shfl_down_sync(0xffffffffu, sum, o);
    if (k == 0) out_len[b] = (float)sum;
}

// K5: copy chain_kernel into the output tail
__global__ void tail_kernel(const float* __restrict__ chain, float* __restrict__ outc)
{
    int i = threadIdx.x + blockIdx.x * blockDim.x;
    if (i < KTAG * KTAG) outc[i] = chain[i];
}

// ---------------------------------------------------------------------------
extern "C" void kernel_launch(void* const* d_in, const int* in_sizes, int n_in,
                              void* d_out, int out_size)
{
    const float* X      = (const float*)d_in[0];
    const int*   mask   = (const int*)d_in[1];
    const float* fwK    = (const float*)d_in[2];
    const float* fwR    = (const float*)d_in[3];
    const float* fwBias = (const float*)d_in[4];
    const float* bwK    = (const float*)d_in[5];
    const float* bwR    = (const float*)d_in[6];
    const float* bwBias = (const float*)d_in[7];
    const float* dK     = (const float*)d_in[8];
    const float* dB     = (const float*)d_in[9];
    const float* chain  = (const float*)d_in[10];
    const float* lb     = (const float*)d_in[11];
    const float* rb     = (const float*)d_in[12];

    float* out       = (float*)d_out;
    float* out_dec   = out;                              // B*T
    float* pot       = out + (size_t)BB * TT;            // B*T*K
    float* out_len   = pot + (size_t)BB * TT * KTAG;     // B
    float* out_chain = out_len + BB;                     // K*K

    cudaFuncSetAttribute(proj_mma, cudaFuncAttributeMaxDynamicSharedMemorySize, SMEM_PROJ);

    prep_x<<<2048, 256>>>(X);
    prep_b<<<NCOMB, 256>>>(fwK, bwK);
    dim3 gp(NCOMB / 128, (BB * TT) / 128);
    proj_mma<<<gp, 256, SMEM_PROJ>>>(fwBias, bwBias);
    dim3 g2(BB / NBAT, 2);
    gru_kernel<<<g2, GH>>>(fwR, bwR, fwBias, bwBias, mask);   // 4th launch -> ncu
    pot_kernel<<<(BB * TT) / 8, 256>>>(dK, dB, lb, rb, pot);
    viterbi_kernel<<<BB, 32>>>(pot, chain, mask, out_dec, out_len);
    tail_kernel<<<4, 256>>>(chain, out_chain);
}